// round 1
// baseline (speedup 1.0000x reference)
#include <cuda_runtime.h>
#include <cstdint>

#define Bn 4
#define Sn 2048
#define Dn 768
#define Hn 12
#define Kn 64

// Scratch: device globals (no cudaMalloc allowed). 4 x 24 MB.
__device__ float g_q[Bn * Hn * Sn * Kn];
__device__ float g_k[Bn * Hn * Sn * Kn];
__device__ float g_v[Bn * Hn * Sn * Kn];
__device__ float g_o[Bn * Hn * Sn * Kn];

__device__ __forceinline__ void fma44(float (&acc)[4][4], const float4 a, const float4 b) {
    acc[0][0] = fmaf(a.x, b.x, acc[0][0]);
    acc[0][1] = fmaf(a.x, b.y, acc[0][1]);
    acc[0][2] = fmaf(a.x, b.z, acc[0][2]);
    acc[0][3] = fmaf(a.x, b.w, acc[0][3]);
    acc[1][0] = fmaf(a.y, b.x, acc[1][0]);
    acc[1][1] = fmaf(a.y, b.y, acc[1][1]);
    acc[1][2] = fmaf(a.y, b.z, acc[1][2]);
    acc[1][3] = fmaf(a.y, b.w, acc[1][3]);
    acc[2][0] = fmaf(a.z, b.x, acc[2][0]);
    acc[2][1] = fmaf(a.z, b.y, acc[2][1]);
    acc[2][2] = fmaf(a.z, b.z, acc[2][2]);
    acc[2][3] = fmaf(a.z, b.w, acc[2][3]);
    acc[3][0] = fmaf(a.w, b.x, acc[3][0]);
    acc[3][1] = fmaf(a.w, b.y, acc[3][1]);
    acc[3][2] = fmaf(a.w, b.z, acc[3][2]);
    acc[3][3] = fmaf(a.w, b.w, acc[3][3]);
}

// ---------------------------------------------------------------------------
// QKV projection: out[b,h,s,k] = sum_d X[b,s,d] * W[h,d,k]
// Grid: (B*S/64, H). Block: 256 threads, 4x4 micro-tile, BK=16.
// ---------------------------------------------------------------------------
__global__ __launch_bounds__(256) void proj_kernel(const float* __restrict__ X,
                                                   const float* __restrict__ W,
                                                   float* __restrict__ out) {
    __shared__ float XsT[16][68];   // [k][row], padded
    __shared__ float Ws[16][64];    // [k][col]

    const int tid = threadIdx.x;
    const int tx4 = (tid & 15) * 4;
    const int ty4 = (tid >> 4) * 4;
    const int row0 = blockIdx.x * 64;
    const int h = blockIdx.y;
    const float* Wh = W + (size_t)h * Dn * Kn;

    const int xr = tid >> 2;            // 0..63
    const int xc = (tid & 3) * 4;       // 0,4,8,12
    const int wr = tid >> 4;            // 0..15
    const int wc = (tid & 15) * 4;      // 0..60

    float acc[4][4] = {};

    for (int kk = 0; kk < Dn; kk += 16) {
        float4 xv = *(const float4*)(X + (size_t)(row0 + xr) * Dn + kk + xc);
        *(float4*)&Ws[wr][wc] = *(const float4*)(Wh + (size_t)(kk + wr) * Kn + wc);
        XsT[xc + 0][xr] = xv.x;
        XsT[xc + 1][xr] = xv.y;
        XsT[xc + 2][xr] = xv.z;
        XsT[xc + 3][xr] = xv.w;
        __syncthreads();
#pragma unroll
        for (int k = 0; k < 16; ++k) {
            float4 a = *(const float4*)&XsT[k][ty4];
            float4 b = *(const float4*)&Ws[k][tx4];
            fma44(acc, a, b);
        }
        __syncthreads();
    }

#pragma unroll
    for (int i = 0; i < 4; ++i) {
        int row = row0 + ty4 + i;          // global row over B*S
        int b = row >> 11;                 // /2048
        int s = row & 2047;
        float* op = out + (((size_t)(b * Hn + h) * Sn + s) * Kn) + tx4;
        *(float4*)op = make_float4(acc[i][0], acc[i][1], acc[i][2], acc[i][3]);
    }
}

// ---------------------------------------------------------------------------
// Flash attention per (b, h, q-tile of 64). Dynamic smem:
//   QsT [64][68] | KsT [64][68] (aliased as PsT) | Vs [64][64]   = 51200 B
// ---------------------------------------------------------------------------
#define ATTN_SMEM ((2 * 64 * 68 + 64 * 64) * 4)

__global__ __launch_bounds__(256) void attn_kernel(const float* __restrict__ mask) {
    extern __shared__ float sm[];
    float* QsT = sm;                 // [64][68]  (d-major, q across)
    float* KsT = sm + 64 * 68;       // [64][68]  (d-major, k across); reused as PsT [k][q]
    float* Vs  = sm + 2 * 64 * 68;   // [64][64]  (k rows, v across)

    const int tid = threadIdx.x;
    const int tx4 = (tid & 15) * 4;
    const int ty4 = (tid >> 4) * 4;
    const int qt = blockIdx.x, h = blockIdx.y, b = blockIdx.z;

    const size_t bh = (size_t)(b * Hn + h) * Sn;
    const float* qp = g_q + (bh + (size_t)qt * 64) * Kn;
    const float* kp = g_k + bh * Kn;
    const float* vp = g_v + bh * Kn;
    float* op = g_o + (bh + (size_t)qt * 64) * Kn;

    // Load Q tile transposed (once per block)
#pragma unroll
    for (int rep = 0; rep < 4; ++rep) {
        int idx = tid + rep * 256;
        int r = idx >> 4, c = (idx & 15) * 4;
        float4 v = *(const float4*)(qp + r * 64 + c);
        QsT[(c + 0) * 68 + r] = v.x;
        QsT[(c + 1) * 68 + r] = v.y;
        QsT[(c + 2) * 68 + r] = v.z;
        QsT[(c + 3) * 68 + r] = v.w;
    }

    float m_i[4], l_i[4], o[4][4];
#pragma unroll
    for (int i = 0; i < 4; ++i) {
        m_i[i] = -1e30f;
        l_i[i] = 0.f;
#pragma unroll
        for (int j = 0; j < 4; ++j) o[i][j] = 0.f;
    }

    const float scale = 0.125f;  // 1/sqrt(64)
    const int qg0 = qt * 64 + ty4;

    for (int kt = 0; kt < Sn / 64; ++kt) {
        __syncthreads();  // previous iteration done reading KsT(PsT)/Vs
        // Load K tile transposed + V tile natural
#pragma unroll
        for (int rep = 0; rep < 4; ++rep) {
            int idx = tid + rep * 256;
            int r = idx >> 4, c = (idx & 15) * 4;
            float4 kv = *(const float4*)(kp + (size_t)(kt * 64 + r) * 64 + c);
            KsT[(c + 0) * 68 + r] = kv.x;
            KsT[(c + 1) * 68 + r] = kv.y;
            KsT[(c + 2) * 68 + r] = kv.z;
            KsT[(c + 3) * 68 + r] = kv.w;
            *(float4*)&Vs[r * 64 + c] = *(const float4*)(vp + (size_t)(kt * 64 + r) * 64 + c);
        }
        __syncthreads();

        // S = Q @ K^T
        float s[4][4] = {};
#pragma unroll 8
        for (int d = 0; d < 64; ++d) {
            float4 a  = *(const float4*)(QsT + d * 68 + ty4);
            float4 bk = *(const float4*)(KsT + d * 68 + tx4);
            fma44(s, a, bk);
        }

        // scale + mask bias
#pragma unroll
        for (int i = 0; i < 4; ++i) {
            const float4 mv = __ldg((const float4*)(mask + (size_t)(qg0 + i) * Sn + kt * 64 + tx4));
            s[i][0] = fmaf(s[i][0], scale, (1.f - mv.x) * -1e9f);
            s[i][1] = fmaf(s[i][1], scale, (1.f - mv.y) * -1e9f);
            s[i][2] = fmaf(s[i][2], scale, (1.f - mv.z) * -1e9f);
            s[i][3] = fmaf(s[i][3], scale, (1.f - mv.w) * -1e9f);
        }

        // online softmax (row = q; 16 lanes sharing ty hold the 64 cols)
#pragma unroll
        for (int i = 0; i < 4; ++i) {
            float mx = fmaxf(fmaxf(s[i][0], s[i][1]), fmaxf(s[i][2], s[i][3]));
#pragma unroll
            for (int w = 1; w < 16; w <<= 1)
                mx = fmaxf(mx, __shfl_xor_sync(0xffffffffu, mx, w));
            float m_new = fmaxf(m_i[i], mx);
            float corr = __expf(m_i[i] - m_new);
            m_i[i] = m_new;
            float ps = 0.f;
#pragma unroll
            for (int j = 0; j < 4; ++j) {
                s[i][j] = __expf(s[i][j] - m_new);
                ps += s[i][j];
            }
#pragma unroll
            for (int w = 1; w < 16; w <<= 1)
                ps += __shfl_xor_sync(0xffffffffu, ps, w);
            l_i[i] = l_i[i] * corr + ps;
#pragma unroll
            for (int j = 0; j < 4; ++j) o[i][j] *= corr;
        }

        __syncthreads();  // all threads done reading KsT
        // Stage P transposed into the K buffer: PsT[k][q]
#pragma unroll
        for (int j = 0; j < 4; ++j) {
            *(float4*)&KsT[(tx4 + j) * 68 + ty4] =
                make_float4(s[0][j], s[1][j], s[2][j], s[3][j]);
        }
        __syncthreads();

        // O += P @ V
#pragma unroll 8
        for (int k = 0; k < 64; ++k) {
            float4 a  = *(const float4*)(KsT + k * 68 + ty4);  // PsT
            float4 bv = *(const float4*)(Vs + k * 64 + tx4);
            fma44(o, a, bv);
        }
    }

    // normalize + store [b,h,s,v]
#pragma unroll
    for (int i = 0; i < 4; ++i) {
        float inv = 1.f / l_i[i];
        *(float4*)(op + (size_t)(ty4 + i) * 64 + tx4) =
            make_float4(o[i][0] * inv, o[i][1] * inv, o[i][2] * inv, o[i][3] * inv);
    }
}

// ---------------------------------------------------------------------------
// Output projection: out[r, d] = sum_f o_flat[r, f] * W_o[f, d]
// o_flat is g_o read raw as [B*S, 768]  (the reference's raw reshape).
// Grid: (B*S/64, 768/64).
// ---------------------------------------------------------------------------
__global__ __launch_bounds__(256) void outproj_kernel(const float* __restrict__ X,
                                                      const float* __restrict__ Wo,
                                                      float* __restrict__ out) {
    __shared__ float XsT[16][68];
    __shared__ float Ws[16][64];

    const int tid = threadIdx.x;
    const int tx4 = (tid & 15) * 4;
    const int ty4 = (tid >> 4) * 4;
    const int row0 = blockIdx.x * 64;
    const int c0 = blockIdx.y * 64;

    const int xr = tid >> 2;
    const int xc = (tid & 3) * 4;
    const int wr = tid >> 4;
    const int wc = (tid & 15) * 4;

    float acc[4][4] = {};

    for (int kk = 0; kk < Dn; kk += 16) {
        float4 xv = *(const float4*)(X + (size_t)(row0 + xr) * Dn + kk + xc);
        *(float4*)&Ws[wr][wc] = *(const float4*)(Wo + (size_t)(kk + wr) * Dn + c0 + wc);
        XsT[xc + 0][xr] = xv.x;
        XsT[xc + 1][xr] = xv.y;
        XsT[xc + 2][xr] = xv.z;
        XsT[xc + 3][xr] = xv.w;
        __syncthreads();
#pragma unroll
        for (int k = 0; k < 16; ++k) {
            float4 a = *(const float4*)&XsT[k][ty4];
            float4 b = *(const float4*)&Ws[k][tx4];
            fma44(acc, a, b);
        }
        __syncthreads();
    }

#pragma unroll
    for (int i = 0; i < 4; ++i) {
        *(float4*)(out + (size_t)(row0 + ty4 + i) * Dn + c0 + tx4) =
            make_float4(acc[i][0], acc[i][1], acc[i][2], acc[i][3]);
    }
}

// ---------------------------------------------------------------------------
extern "C" void kernel_launch(void* const* d_in, const int* in_sizes, int n_in,
                              void* d_out, int out_size) {
    const float* queries = (const float*)d_in[0];
    const float* keys    = (const float*)d_in[1];
    const float* values  = (const float*)d_in[2];
    const float* mask    = (const float*)d_in[3];
    const float* W_q     = (const float*)d_in[4];
    const float* W_k     = (const float*)d_in[5];
    const float* W_v     = (const float*)d_in[6];
    const float* W_o     = (const float*)d_in[7];
    float* out = (float*)d_out;

    float *gq, *gk, *gv, *go;
    cudaGetSymbolAddress((void**)&gq, g_q);
    cudaGetSymbolAddress((void**)&gk, g_k);
    cudaGetSymbolAddress((void**)&gv, g_v);
    cudaGetSymbolAddress((void**)&go, g_o);

    cudaFuncSetAttribute(attn_kernel, cudaFuncAttributeMaxDynamicSharedMemorySize, ATTN_SMEM);

    dim3 gproj(Bn * Sn / 64, Hn);
    proj_kernel<<<gproj, 256>>>(queries, W_q, gq);
    proj_kernel<<<gproj, 256>>>(keys,    W_k, gk);
    proj_kernel<<<gproj, 256>>>(values,  W_v, gv);

    dim3 gattn(Sn / 64, Hn, Bn);
    attn_kernel<<<gattn, 256, ATTN_SMEM>>>(mask);

    dim3 gout(Bn * Sn / 64, Dn / 64);
    outproj_kernel<<<gout, 256>>>(go, W_o, out);
}

// round 2
// speedup vs baseline: 1.0424x; 1.0424x over previous
#include <cuda_runtime.h>
#include <cstdint>

#define Bn 4
#define Sn 2048
#define Dn 768
#define Hn 12
#define Kn 64

// Scratch: device globals (no cudaMalloc allowed). 4 x 24 MB.
__device__ float g_q[Bn * Hn * Sn * Kn];
__device__ float g_k[Bn * Hn * Sn * Kn];
__device__ float g_v[Bn * Hn * Sn * Kn];
__device__ float g_o[Bn * Hn * Sn * Kn];

// ---------------------------------------------------------------------------
// 8x8 FFMA micro-kernel helpers
// ---------------------------------------------------------------------------
__device__ __forceinline__ void fma88(float (&acc)[8][8],
                                      const float4 a0, const float4 a1,
                                      const float4 b0, const float4 b1) {
    float a[8] = {a0.x, a0.y, a0.z, a0.w, a1.x, a1.y, a1.z, a1.w};
    float b[8] = {b0.x, b0.y, b0.z, b0.w, b1.x, b1.y, b1.z, b1.w};
#pragma unroll
    for (int i = 0; i < 8; ++i)
#pragma unroll
        for (int j = 0; j < 8; ++j)
            acc[i][j] = fmaf(a[i], b[j], acc[i][j]);
}

__device__ __forceinline__ void fma84(float (&acc)[8][4],
                                      const float4 a0, const float4 a1,
                                      const float4 b0) {
    float a[8] = {a0.x, a0.y, a0.z, a0.w, a1.x, a1.y, a1.z, a1.w};
    float b[4] = {b0.x, b0.y, b0.z, b0.w};
#pragma unroll
    for (int i = 0; i < 8; ++i)
#pragma unroll
        for (int j = 0; j < 4; ++j)
            acc[i][j] = fmaf(a[i], b[j], acc[i][j]);
}

// ---------------------------------------------------------------------------
// QKV projection as one GEMM: out[b,h,s,k] = sum_d X[b,s,d] * W[h,d,k]
// M = B*S = 8192 rows, "N" = H*K = 768 cols (col c -> head c>>6, k c&63).
// Tile 128x128, BK=16, 256 threads, 8x8 micro-tile.
// ---------------------------------------------------------------------------
__global__ __launch_bounds__(256) void proj_kernel(const float* __restrict__ X,
                                                   const float* __restrict__ W,
                                                   float* __restrict__ out) {
    __shared__ float XsT[16][132];  // [k][row]
    __shared__ float Bs[16][132];   // [k][col]

    const int tid = threadIdx.x;
    const int qr0 = (tid >> 4) * 8;   // 0..120
    const int kc0 = (tid & 15) * 8;   // 0..120
    const int row0 = blockIdx.x * 128;
    const int c0 = blockIdx.y * 128;

    float acc[8][8] = {};

    for (int kk = 0; kk < Dn; kk += 16) {
        // Load X tile transposed: 128 rows x 16 k
#pragma unroll
        for (int rep = 0; rep < 2; ++rep) {
            int idx = tid + rep * 256;
            int r = idx >> 2, c = (idx & 3) * 4;
            float4 xv = *(const float4*)(X + (size_t)(row0 + r) * Dn + kk + c);
            XsT[c + 0][r] = xv.x;
            XsT[c + 1][r] = xv.y;
            XsT[c + 2][r] = xv.z;
            XsT[c + 3][r] = xv.w;
        }
        // Load W tile: 16 k x 128 cols (col -> (h, kidx))
#pragma unroll
        for (int rep = 0; rep < 2; ++rep) {
            int idx = tid + rep * 256;
            int kr = idx >> 5, cc = (idx & 31) * 4;
            int col = c0 + cc;
            int h = col >> 6, kidx = col & 63;
            *(float4*)&Bs[kr][cc] =
                *(const float4*)(W + ((size_t)(h * Dn + kk + kr) * Kn) + kidx);
        }
        __syncthreads();
#pragma unroll
        for (int k = 0; k < 16; ++k) {
            float4 a0 = *(const float4*)&XsT[k][qr0];
            float4 a1 = *(const float4*)&XsT[k][qr0 + 4];
            float4 b0 = *(const float4*)&Bs[k][kc0];
            float4 b1 = *(const float4*)&Bs[k][kc0 + 4];
            fma88(acc, a0, a1, b0, b1);
        }
        __syncthreads();
    }

    const int colg = c0 + kc0;
    const int h = colg >> 6, k0 = colg & 63;  // 8 cols stay within one head
#pragma unroll
    for (int i = 0; i < 8; ++i) {
        int row = row0 + qr0 + i;
        int b = row >> 11, s = row & 2047;
        float* op = out + (((size_t)(b * Hn + h) * Sn + s) * Kn) + k0;
        *(float4*)op = make_float4(acc[i][0], acc[i][1], acc[i][2], acc[i][3]);
        *(float4*)(op + 4) = make_float4(acc[i][4], acc[i][5], acc[i][6], acc[i][7]);
    }
}

// ---------------------------------------------------------------------------
// Flash attention per (b, h, q-tile of 128), k-tiles of 128.
// Smem: QsT[64][132] | KPs[128][132] (KsT then PsT) | Vs[128][64]
// ---------------------------------------------------------------------------
#define ATTN_SMEM ((64 * 132 + 128 * 132 + 128 * 64) * 4)

__global__ __launch_bounds__(256) void attn_kernel(const float* __restrict__ mask) {
    extern __shared__ float sm[];
    float* QsT = sm;                  // [64][132]   (d-major, q across)
    float* KPs = sm + 64 * 132;       // [64][132] as KsT; [128][132] as PsT
    float* Vs  = sm + 64 * 132 + 128 * 132;  // [128][64]

    const int tid = threadIdx.x;
    const int ty = tid >> 4, tx = tid & 15;
    const int qr0 = ty * 8;           // local q row base
    const int kc0 = tx * 8;           // local k col base
    const int vc0 = tx * 4;           // local v col base
    const int qt = blockIdx.x, h = blockIdx.y, b = blockIdx.z;

    const size_t bh = (size_t)(b * Hn + h) * Sn;
    const float* qp = g_q + (bh + (size_t)qt * 128) * Kn;
    const float* kp = g_k + bh * Kn;
    const float* vp = g_v + bh * Kn;
    float* op = g_o + (bh + (size_t)qt * 128) * Kn;

    // Load Q tile transposed (once): 128 rows x 64 d
#pragma unroll
    for (int rep = 0; rep < 8; ++rep) {
        int idx = tid + rep * 256;
        int r = idx >> 4, c = (idx & 15) * 4;
        float4 v = *(const float4*)(qp + (size_t)r * 64 + c);
        QsT[(c + 0) * 132 + r] = v.x;
        QsT[(c + 1) * 132 + r] = v.y;
        QsT[(c + 2) * 132 + r] = v.z;
        QsT[(c + 3) * 132 + r] = v.w;
    }

    float m_i[8], l_i[8], o[8][4];
#pragma unroll
    for (int i = 0; i < 8; ++i) {
        m_i[i] = -1e30f;
        l_i[i] = 0.f;
#pragma unroll
        for (int j = 0; j < 4; ++j) o[i][j] = 0.f;
    }

    const float scale = 0.125f;  // 1/sqrt(64)
    const int qg0 = qt * 128 + qr0;

    for (int kt = 0; kt < Sn / 128; ++kt) {
        __syncthreads();  // prev iteration done reading PsT/Vs
        // Load K tile transposed (128 rows x 64 d) + V tile natural
#pragma unroll
        for (int rep = 0; rep < 8; ++rep) {
            int idx = tid + rep * 256;
            int r = idx >> 4, c = (idx & 15) * 4;
            float4 kv = *(const float4*)(kp + (size_t)(kt * 128 + r) * 64 + c);
            KPs[(c + 0) * 132 + r] = kv.x;
            KPs[(c + 1) * 132 + r] = kv.y;
            KPs[(c + 2) * 132 + r] = kv.z;
            KPs[(c + 3) * 132 + r] = kv.w;
            *(float4*)&Vs[r * 64 + c] = *(const float4*)(vp + (size_t)(kt * 128 + r) * 64 + c);
        }
        __syncthreads();

        // S = Q @ K^T  (8x8 per thread)
        float s[8][8] = {};
#pragma unroll 8
        for (int d = 0; d < 64; ++d) {
            float4 a0 = *(const float4*)(QsT + d * 132 + qr0);
            float4 a1 = *(const float4*)(QsT + d * 132 + qr0 + 4);
            float4 b0 = *(const float4*)(KPs + d * 132 + kc0);
            float4 b1 = *(const float4*)(KPs + d * 132 + kc0 + 4);
            fma88(s, a0, a1, b0, b1);
        }

        // scale + mask bias + online softmax
#pragma unroll
        for (int i = 0; i < 8; ++i) {
            const float* mrow = mask + (size_t)(qg0 + i) * Sn + kt * 128 + kc0;
            const float4 mv0 = __ldg((const float4*)mrow);
            const float4 mv1 = __ldg((const float4*)(mrow + 4));
            s[i][0] = fmaf(s[i][0], scale, (1.f - mv0.x) * -1e9f);
            s[i][1] = fmaf(s[i][1], scale, (1.f - mv0.y) * -1e9f);
            s[i][2] = fmaf(s[i][2], scale, (1.f - mv0.z) * -1e9f);
            s[i][3] = fmaf(s[i][3], scale, (1.f - mv0.w) * -1e9f);
            s[i][4] = fmaf(s[i][4], scale, (1.f - mv1.x) * -1e9f);
            s[i][5] = fmaf(s[i][5], scale, (1.f - mv1.y) * -1e9f);
            s[i][6] = fmaf(s[i][6], scale, (1.f - mv1.z) * -1e9f);
            s[i][7] = fmaf(s[i][7], scale, (1.f - mv1.w) * -1e9f);

            float mx = s[i][0];
#pragma unroll
            for (int j = 1; j < 8; ++j) mx = fmaxf(mx, s[i][j]);
#pragma unroll
            for (int w = 1; w < 16; w <<= 1)
                mx = fmaxf(mx, __shfl_xor_sync(0xffffffffu, mx, w));
            float m_new = fmaxf(m_i[i], mx);
            float corr = __expf(m_i[i] - m_new);
            m_i[i] = m_new;
            float ps = 0.f;
#pragma unroll
            for (int j = 0; j < 8; ++j) {
                s[i][j] = __expf(s[i][j] - m_new);
                ps += s[i][j];
            }
#pragma unroll
            for (int w = 1; w < 16; w <<= 1)
                ps += __shfl_xor_sync(0xffffffffu, ps, w);
            l_i[i] = l_i[i] * corr + ps;
#pragma unroll
            for (int j = 0; j < 4; ++j) o[i][j] *= corr;
        }

        __syncthreads();  // all threads done reading KsT
        // Stage P transposed: PsT[k][q]
#pragma unroll
        for (int j = 0; j < 8; ++j) {
            *(float4*)&KPs[(kc0 + j) * 132 + qr0] =
                make_float4(s[0][j], s[1][j], s[2][j], s[3][j]);
            *(float4*)&KPs[(kc0 + j) * 132 + qr0 + 4] =
                make_float4(s[4][j], s[5][j], s[6][j], s[7][j]);
        }
        __syncthreads();

        // O += P @ V  (8x4 per thread)
#pragma unroll 8
        for (int k = 0; k < 128; ++k) {
            float4 a0 = *(const float4*)(KPs + k * 132 + qr0);
            float4 a1 = *(const float4*)(KPs + k * 132 + qr0 + 4);
            float4 bv = *(const float4*)(Vs + k * 64 + vc0);
            fma84(o, a0, a1, bv);
        }
    }

    // normalize + store [b,h,s,v]
#pragma unroll
    for (int i = 0; i < 8; ++i) {
        float inv = 1.f / l_i[i];
        *(float4*)(op + (size_t)(qr0 + i) * 64 + vc0) =
            make_float4(o[i][0] * inv, o[i][1] * inv, o[i][2] * inv, o[i][3] * inv);
    }
}

// ---------------------------------------------------------------------------
// Output projection: out[r, d] = sum_f o_flat[r, f] * W_o[f, d]
// o_flat is g_o read raw as [B*S, 768]  (the reference's raw reshape).
// Tile 128x128, BK=16, 8x8 micro-tile.
// ---------------------------------------------------------------------------
__global__ __launch_bounds__(256) void outproj_kernel(const float* __restrict__ X,
                                                      const float* __restrict__ Wo,
                                                      float* __restrict__ out) {
    __shared__ float XsT[16][132];
    __shared__ float Bs[16][132];

    const int tid = threadIdx.x;
    const int qr0 = (tid >> 4) * 8;
    const int kc0 = (tid & 15) * 8;
    const int row0 = blockIdx.x * 128;
    const int c0 = blockIdx.y * 128;

    float acc[8][8] = {};

    for (int kk = 0; kk < Dn; kk += 16) {
#pragma unroll
        for (int rep = 0; rep < 2; ++rep) {
            int idx = tid + rep * 256;
            int r = idx >> 2, c = (idx & 3) * 4;
            float4 xv = *(const float4*)(X + (size_t)(row0 + r) * Dn + kk + c);
            XsT[c + 0][r] = xv.x;
            XsT[c + 1][r] = xv.y;
            XsT[c + 2][r] = xv.z;
            XsT[c + 3][r] = xv.w;
        }
#pragma unroll
        for (int rep = 0; rep < 2; ++rep) {
            int idx = tid + rep * 256;
            int kr = idx >> 5, cc = (idx & 31) * 4;
            *(float4*)&Bs[kr][cc] =
                *(const float4*)(Wo + (size_t)(kk + kr) * Dn + c0 + cc);
        }
        __syncthreads();
#pragma unroll
        for (int k = 0; k < 16; ++k) {
            float4 a0 = *(const float4*)&XsT[k][qr0];
            float4 a1 = *(const float4*)&XsT[k][qr0 + 4];
            float4 b0 = *(const float4*)&Bs[k][kc0];
            float4 b1 = *(const float4*)&Bs[k][kc0 + 4];
            fma88(acc, a0, a1, b0, b1);
        }
        __syncthreads();
    }

#pragma unroll
    for (int i = 0; i < 8; ++i) {
        float* op = out + (size_t)(row0 + qr0 + i) * Dn + c0 + kc0;
        *(float4*)op = make_float4(acc[i][0], acc[i][1], acc[i][2], acc[i][3]);
        *(float4*)(op + 4) = make_float4(acc[i][4], acc[i][5], acc[i][6], acc[i][7]);
    }
}

// ---------------------------------------------------------------------------
extern "C" void kernel_launch(void* const* d_in, const int* in_sizes, int n_in,
                              void* d_out, int out_size) {
    const float* queries = (const float*)d_in[0];
    const float* keys    = (const float*)d_in[1];
    const float* values  = (const float*)d_in[2];
    const float* mask    = (const float*)d_in[3];
    const float* W_q     = (const float*)d_in[4];
    const float* W_k     = (const float*)d_in[5];
    const float* W_v     = (const float*)d_in[6];
    const float* W_o     = (const float*)d_in[7];
    float* out = (float*)d_out;

    float *gq, *gk, *gv, *go;
    cudaGetSymbolAddress((void**)&gq, g_q);
    cudaGetSymbolAddress((void**)&gk, g_k);
    cudaGetSymbolAddress((void**)&gv, g_v);
    cudaGetSymbolAddress((void**)&go, g_o);

    cudaFuncSetAttribute(attn_kernel, cudaFuncAttributeMaxDynamicSharedMemorySize, ATTN_SMEM);

    dim3 gproj(Bn * Sn / 128, Dn / 128);  // (64, 6)
    proj_kernel<<<gproj, 256>>>(queries, W_q, gq);
    proj_kernel<<<gproj, 256>>>(keys,    W_k, gk);
    proj_kernel<<<gproj, 256>>>(values,  W_v, gv);

    dim3 gattn(Sn / 128, Hn, Bn);  // (16, 12, 4)
    attn_kernel<<<gattn, 256, ATTN_SMEM>>>(mask);

    dim3 gout(Bn * Sn / 128, Dn / 128);  // (64, 6)
    outproj_kernel<<<gout, 256>>>(go, W_o, out);
}

// round 3
// speedup vs baseline: 1.0436x; 1.0011x over previous
#include <cuda_runtime.h>
#include <cstdint>

#define Bn 4
#define Sn 2048
#define Dn 768
#define Hn 12
#define Kn 64

// Scratch: device globals (no cudaMalloc allowed). 4 x 24 MB.
__device__ float g_q[Bn * Hn * Sn * Kn];
__device__ float g_k[Bn * Hn * Sn * Kn];
__device__ float g_v[Bn * Hn * Sn * Kn];
__device__ float g_o[Bn * Hn * Sn * Kn];

// ---------------------------------------------------------------------------
// 8x8 FFMA micro-kernel helpers
// ---------------------------------------------------------------------------
__device__ __forceinline__ void fma88(float (&acc)[8][8],
                                      const float4 a0, const float4 a1,
                                      const float4 b0, const float4 b1) {
    float a[8] = {a0.x, a0.y, a0.z, a0.w, a1.x, a1.y, a1.z, a1.w};
    float b[8] = {b0.x, b0.y, b0.z, b0.w, b1.x, b1.y, b1.z, b1.w};
#pragma unroll
    for (int i = 0; i < 8; ++i)
#pragma unroll
        for (int j = 0; j < 8; ++j)
            acc[i][j] = fmaf(a[i], b[j], acc[i][j]);
}

__device__ __forceinline__ void fma84(float (&acc)[8][4],
                                      const float4 a0, const float4 a1,
                                      const float4 b0) {
    float a[8] = {a0.x, a0.y, a0.z, a0.w, a1.x, a1.y, a1.z, a1.w};
    float b[4] = {b0.x, b0.y, b0.z, b0.w};
#pragma unroll
    for (int i = 0; i < 8; ++i)
#pragma unroll
        for (int j = 0; j < 4; ++j)
            acc[i][j] = fmaf(a[i], b[j], acc[i][j]);
}

// ---------------------------------------------------------------------------
// QKV projection as one GEMM: out[b,h,s,k] = sum_d X[b,s,d] * W[h,d,k]
// M = B*S = 8192 rows, "N" = H*K = 768 cols (col c -> head c>>6, k c&63).
// Tile 128x128, BK=16, 256 threads, 8x8 micro-tile.
// ---------------------------------------------------------------------------
__global__ __launch_bounds__(256) void proj_kernel(const float* __restrict__ X,
                                                   const float* __restrict__ W,
                                                   float* __restrict__ out) {
    __shared__ float XsT[16][132];  // [k][row]
    __shared__ float Bs[16][132];   // [k][col]

    const int tid = threadIdx.x;
    const int qr0 = (tid >> 4) * 8;   // 0..120
    const int kc0 = (tid & 15) * 8;   // 0..120
    const int row0 = blockIdx.x * 128;
    const int c0 = blockIdx.y * 128;

    float acc[8][8] = {};

    for (int kk = 0; kk < Dn; kk += 16) {
        // Load X tile transposed: 128 rows x 16 k
#pragma unroll
        for (int rep = 0; rep < 2; ++rep) {
            int idx = tid + rep * 256;
            int r = idx >> 2, c = (idx & 3) * 4;
            float4 xv = *(const float4*)(X + (size_t)(row0 + r) * Dn + kk + c);
            XsT[c + 0][r] = xv.x;
            XsT[c + 1][r] = xv.y;
            XsT[c + 2][r] = xv.z;
            XsT[c + 3][r] = xv.w;
        }
        // Load W tile: 16 k x 128 cols (col -> (h, kidx))
#pragma unroll
        for (int rep = 0; rep < 2; ++rep) {
            int idx = tid + rep * 256;
            int kr = idx >> 5, cc = (idx & 31) * 4;
            int col = c0 + cc;
            int h = col >> 6, kidx = col & 63;
            *(float4*)&Bs[kr][cc] =
                *(const float4*)(W + ((size_t)(h * Dn + kk + kr) * Kn) + kidx);
        }
        __syncthreads();
#pragma unroll
        for (int k = 0; k < 16; ++k) {
            float4 a0 = *(const float4*)&XsT[k][qr0];
            float4 a1 = *(const float4*)&XsT[k][qr0 + 4];
            float4 b0 = *(const float4*)&Bs[k][kc0];
            float4 b1 = *(const float4*)&Bs[k][kc0 + 4];
            fma88(acc, a0, a1, b0, b1);
        }
        __syncthreads();
    }

    const int colg = c0 + kc0;
    const int h = colg >> 6, k0 = colg & 63;  // 8 cols stay within one head
#pragma unroll
    for (int i = 0; i < 8; ++i) {
        int row = row0 + qr0 + i;
        int b = row >> 11, s = row & 2047;
        float* op = out + (((size_t)(b * Hn + h) * Sn + s) * Kn) + k0;
        *(float4*)op = make_float4(acc[i][0], acc[i][1], acc[i][2], acc[i][3]);
        *(float4*)(op + 4) = make_float4(acc[i][4], acc[i][5], acc[i][6], acc[i][7]);
    }
}

// ---------------------------------------------------------------------------
// Flash attention per (b, h, q-tile of 128), k-tiles of 128.
// Smem: QsT[64][132] | KPs[128][132] (KsT then PsT) | Vs[128][64]
// ---------------------------------------------------------------------------
#define ATTN_SMEM ((64 * 132 + 128 * 132 + 128 * 64) * 4)

__global__ __launch_bounds__(256) void attn_kernel(const float* __restrict__ mask) {
    extern __shared__ float sm[];
    float* QsT = sm;                  // [64][132]   (d-major, q across)
    float* KPs = sm + 64 * 132;       // [64][132] as KsT; [128][132] as PsT
    float* Vs  = sm + 64 * 132 + 128 * 132;  // [128][64]

    const int tid = threadIdx.x;
    const int ty = tid >> 4, tx = tid & 15;
    const int qr0 = ty * 8;           // local q row base
    const int kc0 = tx * 8;           // local k col base
    const int vc0 = tx * 4;           // local v col base
    const int qt = blockIdx.x, h = blockIdx.y, b = blockIdx.z;

    const size_t bh = (size_t)(b * Hn + h) * Sn;
    const float* qp = g_q + (bh + (size_t)qt * 128) * Kn;
    const float* kp = g_k + bh * Kn;
    const float* vp = g_v + bh * Kn;
    float* op = g_o + (bh + (size_t)qt * 128) * Kn;

    // Load Q tile transposed (once): 128 rows x 64 d
#pragma unroll
    for (int rep = 0; rep < 8; ++rep) {
        int idx = tid + rep * 256;
        int r = idx >> 4, c = (idx & 15) * 4;
        float4 v = *(const float4*)(qp + (size_t)r * 64 + c);
        QsT[(c + 0) * 132 + r] = v.x;
        QsT[(c + 1) * 132 + r] = v.y;
        QsT[(c + 2) * 132 + r] = v.z;
        QsT[(c + 3) * 132 + r] = v.w;
    }

    float m_i[8], l_i[8], o[8][4];
#pragma unroll
    for (int i = 0; i < 8; ++i) {
        m_i[i] = -1e30f;
        l_i[i] = 0.f;
#pragma unroll
        for (int j = 0; j < 4; ++j) o[i][j] = 0.f;
    }

    const float scale = 0.125f;  // 1/sqrt(64)
    const int qg0 = qt * 128 + qr0;

    for (int kt = 0; kt < Sn / 128; ++kt) {
        __syncthreads();  // prev iteration done reading PsT/Vs
        // Load K tile transposed (128 rows x 64 d) + V tile natural
#pragma unroll
        for (int rep = 0; rep < 8; ++rep) {
            int idx = tid + rep * 256;
            int r = idx >> 4, c = (idx & 15) * 4;
            float4 kv = *(const float4*)(kp + (size_t)(kt * 128 + r) * 64 + c);
            KPs[(c + 0) * 132 + r] = kv.x;
            KPs[(c + 1) * 132 + r] = kv.y;
            KPs[(c + 2) * 132 + r] = kv.z;
            KPs[(c + 3) * 132 + r] = kv.w;
            *(float4*)&Vs[r * 64 + c] = *(const float4*)(vp + (size_t)(kt * 128 + r) * 64 + c);
        }
        __syncthreads();

        // S = Q @ K^T  (8x8 per thread)
        float s[8][8] = {};
#pragma unroll 8
        for (int d = 0; d < 64; ++d) {
            float4 a0 = *(const float4*)(QsT + d * 132 + qr0);
            float4 a1 = *(const float4*)(QsT + d * 132 + qr0 + 4);
            float4 b0 = *(const float4*)(KPs + d * 132 + kc0);
            float4 b1 = *(const float4*)(KPs + d * 132 + kc0 + 4);
            fma88(s, a0, a1, b0, b1);
        }

        // scale + mask bias + online softmax
#pragma unroll
        for (int i = 0; i < 8; ++i) {
            const float* mrow = mask + (size_t)(qg0 + i) * Sn + kt * 128 + kc0;
            const float4 mv0 = __ldg((const float4*)mrow);
            const float4 mv1 = __ldg((const float4*)(mrow + 4));
            s[i][0] = fmaf(s[i][0], scale, (1.f - mv0.x) * -1e9f);
            s[i][1] = fmaf(s[i][1], scale, (1.f - mv0.y) * -1e9f);
            s[i][2] = fmaf(s[i][2], scale, (1.f - mv0.z) * -1e9f);
            s[i][3] = fmaf(s[i][3], scale, (1.f - mv0.w) * -1e9f);
            s[i][4] = fmaf(s[i][4], scale, (1.f - mv1.x) * -1e9f);
            s[i][5] = fmaf(s[i][5], scale, (1.f - mv1.y) * -1e9f);
            s[i][6] = fmaf(s[i][6], scale, (1.f - mv1.z) * -1e9f);
            s[i][7] = fmaf(s[i][7], scale, (1.f - mv1.w) * -1e9f);

            float mx = s[i][0];
#pragma unroll
            for (int j = 1; j < 8; ++j) mx = fmaxf(mx, s[i][j]);
#pragma unroll
            for (int w = 1; w < 16; w <<= 1)
                mx = fmaxf(mx, __shfl_xor_sync(0xffffffffu, mx, w));
            float m_new = fmaxf(m_i[i], mx);
            float corr = __expf(m_i[i] - m_new);
            m_i[i] = m_new;
            float ps = 0.f;
#pragma unroll
            for (int j = 0; j < 8; ++j) {
                s[i][j] = __expf(s[i][j] - m_new);
                ps += s[i][j];
            }
#pragma unroll
            for (int w = 1; w < 16; w <<= 1)
                ps += __shfl_xor_sync(0xffffffffu, ps, w);
            l_i[i] = l_i[i] * corr + ps;
#pragma unroll
            for (int j = 0; j < 4; ++j) o[i][j] *= corr;
        }

        __syncthreads();  // all threads done reading KsT
        // Stage P transposed: PsT[k][q]
#pragma unroll
        for (int j = 0; j < 8; ++j) {
            *(float4*)&KPs[(kc0 + j) * 132 + qr0] =
                make_float4(s[0][j], s[1][j], s[2][j], s[3][j]);
            *(float4*)&KPs[(kc0 + j) * 132 + qr0 + 4] =
                make_float4(s[4][j], s[5][j], s[6][j], s[7][j]);
        }
        __syncthreads();

        // O += P @ V  (8x4 per thread)
#pragma unroll 8
        for (int k = 0; k < 128; ++k) {
            float4 a0 = *(const float4*)(KPs + k * 132 + qr0);
            float4 a1 = *(const float4*)(KPs + k * 132 + qr0 + 4);
            float4 bv = *(const float4*)(Vs + k * 64 + vc0);
            fma84(o, a0, a1, bv);
        }
    }

    // normalize + store [b,h,s,v]
#pragma unroll
    for (int i = 0; i < 8; ++i) {
        float inv = 1.f / l_i[i];
        *(float4*)(op + (size_t)(qr0 + i) * 64 + vc0) =
            make_float4(o[i][0] * inv, o[i][1] * inv, o[i][2] * inv, o[i][3] * inv);
    }
}

// ---------------------------------------------------------------------------
// Output projection: out[r, d] = sum_f o_flat[r, f] * W_o[f, d]
// o_flat is g_o read raw as [B*S, 768]  (the reference's raw reshape).
// Tile 128x128, BK=16, 8x8 micro-tile.
// ---------------------------------------------------------------------------
__global__ __launch_bounds__(256) void outproj_kernel(const float* __restrict__ X,
                                                      const float* __restrict__ Wo,
                                                      float* __restrict__ out) {
    __shared__ float XsT[16][132];
    __shared__ float Bs[16][132];

    const int tid = threadIdx.x;
    const int qr0 = (tid >> 4) * 8;
    const int kc0 = (tid & 15) * 8;
    const int row0 = blockIdx.x * 128;
    const int c0 = blockIdx.y * 128;

    float acc[8][8] = {};

    for (int kk = 0; kk < Dn; kk += 16) {
#pragma unroll
        for (int rep = 0; rep < 2; ++rep) {
            int idx = tid + rep * 256;
            int r = idx >> 2, c = (idx & 3) * 4;
            float4 xv = *(const float4*)(X + (size_t)(row0 + r) * Dn + kk + c);
            XsT[c + 0][r] = xv.x;
            XsT[c + 1][r] = xv.y;
            XsT[c + 2][r] = xv.z;
            XsT[c + 3][r] = xv.w;
        }
#pragma unroll
        for (int rep = 0; rep < 2; ++rep) {
            int idx = tid + rep * 256;
            int kr = idx >> 5, cc = (idx & 31) * 4;
            *(float4*)&Bs[kr][cc] =
                *(const float4*)(Wo + (size_t)(kk + kr) * Dn + c0 + cc);
        }
        __syncthreads();
#pragma unroll
        for (int k = 0; k < 16; ++k) {
            float4 a0 = *(const float4*)&XsT[k][qr0];
            float4 a1 = *(const float4*)&XsT[k][qr0 + 4];
            float4 b0 = *(const float4*)&Bs[k][kc0];
            float4 b1 = *(const float4*)&Bs[k][kc0 + 4];
            fma88(acc, a0, a1, b0, b1);
        }
        __syncthreads();
    }

#pragma unroll
    for (int i = 0; i < 8; ++i) {
        float* op = out + (size_t)(row0 + qr0 + i) * Dn + c0 + kc0;
        *(float4*)op = make_float4(acc[i][0], acc[i][1], acc[i][2], acc[i][3]);
        *(float4*)(op + 4) = make_float4(acc[i][4], acc[i][5], acc[i][6], acc[i][7]);
    }
}

// ---------------------------------------------------------------------------
extern "C" void kernel_launch(void* const* d_in, const int* in_sizes, int n_in,
                              void* d_out, int out_size) {
    const float* queries = (const float*)d_in[0];
    const float* keys    = (const float*)d_in[1];
    const float* values  = (const float*)d_in[2];
    const float* mask    = (const float*)d_in[3];
    const float* W_q     = (const float*)d_in[4];
    const float* W_k     = (const float*)d_in[5];
    const float* W_v     = (const float*)d_in[6];
    const float* W_o     = (const float*)d_in[7];
    float* out = (float*)d_out;

    float *gq, *gk, *gv, *go;
    cudaGetSymbolAddress((void**)&gq, g_q);
    cudaGetSymbolAddress((void**)&gk, g_k);
    cudaGetSymbolAddress((void**)&gv, g_v);
    cudaGetSymbolAddress((void**)&go, g_o);

    cudaFuncSetAttribute(attn_kernel, cudaFuncAttributeMaxDynamicSharedMemorySize, ATTN_SMEM);

    dim3 gproj(Bn * Sn / 128, Dn / 128);  // (64, 6)
    proj_kernel<<<gproj, 256>>>(queries, W_q, gq);
    proj_kernel<<<gproj, 256>>>(keys,    W_k, gk);
    proj_kernel<<<gproj, 256>>>(values,  W_v, gv);

    dim3 gattn(Sn / 128, Hn, Bn);  // (16, 12, 4)
    attn_kernel<<<gattn, 256, ATTN_SMEM>>>(mask);

    dim3 gout(Bn * Sn / 128, Dn / 128);  // (64, 6)
    outproj_kernel<<<gout, 256>>>(go, W_o, out);
}

// round 5
// speedup vs baseline: 1.6158x; 1.5483x over previous
#include <cuda_runtime.h>
#include <cuda_bf16.h>
#include <cstdint>

#define Bn 4
#define Sn 2048
#define Dn 768
#define Hn 12
#define Kn 64
#define NELEM (Bn * Hn * Sn * Kn)

// Scratch device globals (no cudaMalloc allowed).
__device__ __nv_bfloat16 g_qh[NELEM], g_ql[NELEM];
__device__ __nv_bfloat16 g_kh[NELEM], g_kl[NELEM];
__device__ __nv_bfloat16 g_vh[NELEM], g_vl[NELEM];
__device__ float g_o[NELEM];

// ---------------------------------------------------------------------------
// helpers
// ---------------------------------------------------------------------------
__device__ __forceinline__ uint32_t smem_u32(const void* p) {
    uint32_t a;
    asm("{ .reg .u64 t; cvta.to.shared.u64 t, %1; cvt.u32.u64 %0, t; }" : "=r"(a) : "l"(p));
    return a;
}
__device__ __forceinline__ void ldsm_x4(uint32_t (&r)[4], uint32_t addr) {
    asm volatile("ldmatrix.sync.aligned.m8n8.x4.shared.b16 {%0,%1,%2,%3}, [%4];"
                 : "=r"(r[0]), "=r"(r[1]), "=r"(r[2]), "=r"(r[3]) : "r"(addr));
}
__device__ __forceinline__ void ldsm_x2(uint32_t (&r)[2], uint32_t addr) {
    asm volatile("ldmatrix.sync.aligned.m8n8.x2.shared.b16 {%0,%1}, [%2];"
                 : "=r"(r[0]), "=r"(r[1]) : "r"(addr));
}
__device__ __forceinline__ void ldsm_x2t(uint32_t (&r)[2], uint32_t addr) {
    asm volatile("ldmatrix.sync.aligned.m8n8.x2.trans.shared.b16 {%0,%1}, [%2];"
                 : "=r"(r[0]), "=r"(r[1]) : "r"(addr));
}
__device__ __forceinline__ void mma_bf16(float (&d)[4], const uint32_t (&a)[4],
                                         const uint32_t (&b)[2]) {
    asm volatile(
        "mma.sync.aligned.m16n8k16.row.col.f32.bf16.bf16.f32 "
        "{%0,%1,%2,%3}, {%4,%5,%6,%7}, {%8,%9}, {%0,%1,%2,%3};"
        : "+f"(d[0]), "+f"(d[1]), "+f"(d[2]), "+f"(d[3])
        : "r"(a[0]), "r"(a[1]), "r"(a[2]), "r"(a[3]), "r"(b[0]), "r"(b[1]));
}
__device__ __forceinline__ void split2(float x, float y, uint32_t& h, uint32_t& l) {
    __nv_bfloat16 hx = __float2bfloat16(x), hy = __float2bfloat16(y);
    __nv_bfloat16 lx = __float2bfloat16(x - __bfloat162float(hx));
    __nv_bfloat16 ly = __float2bfloat16(y - __bfloat162float(hy));
    __nv_bfloat162 hh = __halves2bfloat162(hx, hy);
    __nv_bfloat162 ll = __halves2bfloat162(lx, ly);
    h = *(uint32_t*)&hh;
    l = *(uint32_t*)&ll;
}

// SMEM tile row stride (bf16 elems): 72 -> 144 B rows, ldmatrix conflict-free
#define QS 72
#define TILE_E (128 * QS)
#define ATTN_SMEM (6 * TILE_E * 2)

// ---------------------------------------------------------------------------
// mma.sync flash attention per (b, h, q-tile of 128); k-tiles of 128.
// 256 threads = 8 warps, warp w owns q rows [16w, 16w+16).
// ---------------------------------------------------------------------------
__global__ __launch_bounds__(256, 1) void attn_kernel(const float* __restrict__ mask) {
    extern __shared__ __nv_bfloat16 smbf[];
    __nv_bfloat16* Qh = smbf;
    __nv_bfloat16* Ql = Qh + TILE_E;
    __nv_bfloat16* Kh = Ql + TILE_E;
    __nv_bfloat16* Kl = Kh + TILE_E;
    __nv_bfloat16* Vh = Kl + TILE_E;
    __nv_bfloat16* Vl = Vh + TILE_E;

    const uint32_t sQh = smem_u32(Qh), sQl = smem_u32(Ql);
    const uint32_t sKh = smem_u32(Kh), sKl = smem_u32(Kl);
    const uint32_t sVh = smem_u32(Vh), sVl = smem_u32(Vl);

    const int tid = threadIdx.x;
    const int wid = tid >> 5, lane = tid & 31;
    const int l16 = lane & 15;
    const int r0 = lane >> 2;        // accum row within m16 (and +8)
    const int c2 = (lane & 3) * 2;   // accum col pair within n8
    const int qt = blockIdx.x, hd = blockIdx.y, b = blockIdx.z;
    const size_t bh = (size_t)(b * Hn + hd) * Sn;
    const int qr0 = wid * 16;
    const int qg0 = qt * 128 + qr0;

    // Load Q tile hi/lo (128 x 64), once.
    {
        const __nv_bfloat16* qh = g_qh + (bh + (size_t)qt * 128) * Kn;
        const __nv_bfloat16* ql = g_ql + (bh + (size_t)qt * 128) * Kn;
#pragma unroll
        for (int rep = 0; rep < 4; ++rep) {
            int idx = tid + rep * 256;
            int r = idx >> 3, c8 = (idx & 7) * 8;
            *(uint4*)(Qh + r * QS + c8) = *(const uint4*)(qh + r * 64 + c8);
            *(uint4*)(Ql + r * QS + c8) = *(const uint4*)(ql + r * 64 + c8);
        }
    }

    float oacc[8][4];
#pragma unroll
    for (int n = 0; n < 8; ++n)
#pragma unroll
        for (int j = 0; j < 4; ++j) oacc[n][j] = 0.f;
    float m0 = -1e30f, m1 = -1e30f, l0 = 0.f, l1 = 0.f;

    const float* mp0 = mask + (size_t)(qg0 + r0) * Sn;
    const float* mp1 = mp0 + 8 * Sn;
    const float scale = 0.125f;

    for (int kt = 0; kt < Sn / 128; ++kt) {
        __syncthreads();  // previous iteration finished reading K/V smem
        {
            const __nv_bfloat16* kh = g_kh + (bh + (size_t)kt * 128) * Kn;
            const __nv_bfloat16* kl = g_kl + (bh + (size_t)kt * 128) * Kn;
            const __nv_bfloat16* vh = g_vh + (bh + (size_t)kt * 128) * Kn;
            const __nv_bfloat16* vl = g_vl + (bh + (size_t)kt * 128) * Kn;
#pragma unroll
            for (int rep = 0; rep < 4; ++rep) {
                int idx = tid + rep * 256;
                int r = idx >> 3, c8 = (idx & 7) * 8;
                *(uint4*)(Kh + r * QS + c8) = *(const uint4*)(kh + r * 64 + c8);
                *(uint4*)(Kl + r * QS + c8) = *(const uint4*)(kl + r * 64 + c8);
                *(uint4*)(Vh + r * QS + c8) = *(const uint4*)(vh + r * 64 + c8);
                *(uint4*)(Vl + r * QS + c8) = *(const uint4*)(vl + r * 64 + c8);
            }
        }
        __syncthreads();

        // ---- S = Q @ K^T  (m16 x n128 per warp, k64, 3 split terms) ----
        float sacc[16][4];
#pragma unroll
        for (int n = 0; n < 16; ++n)
#pragma unroll
            for (int j = 0; j < 4; ++j) sacc[n][j] = 0.f;

#pragma unroll
        for (int ks = 0; ks < 4; ++ks) {
            uint32_t aqh[4], aql[4];
            const uint32_t aoff =
                (uint32_t)(((qr0 + l16) * QS + ks * 16 + (lane >> 4) * 8) * 2);
            ldsm_x4(aqh, sQh + aoff);
            ldsm_x4(aql, sQl + aoff);
#pragma unroll
            for (int n = 0; n < 16; ++n) {
                const uint32_t boff =
                    (uint32_t)(((n * 8 + (l16 & 7)) * QS + ks * 16 + (l16 >> 3) * 8) * 2);
                uint32_t bkh[2], bkl[2];
                ldsm_x2(bkh, sKh + boff);
                ldsm_x2(bkl, sKl + boff);
                mma_bf16(sacc[n], aqh, bkh);
                mma_bf16(sacc[n], aqh, bkl);
                mma_bf16(sacc[n], aql, bkh);
            }
        }

        // ---- scale + mask bias + online softmax ----
        float rmax0 = -1e30f, rmax1 = -1e30f;
#pragma unroll
        for (int n = 0; n < 16; ++n) {
            const int col = kt * 128 + n * 8 + c2;
            float2 mv0 = __ldg((const float2*)(mp0 + col));
            float2 mv1 = __ldg((const float2*)(mp1 + col));
            sacc[n][0] = fmaf(sacc[n][0], scale, (1.f - mv0.x) * -1e9f);
            sacc[n][1] = fmaf(sacc[n][1], scale, (1.f - mv0.y) * -1e9f);
            sacc[n][2] = fmaf(sacc[n][2], scale, (1.f - mv1.x) * -1e9f);
            sacc[n][3] = fmaf(sacc[n][3], scale, (1.f - mv1.y) * -1e9f);
            rmax0 = fmaxf(rmax0, fmaxf(sacc[n][0], sacc[n][1]));
            rmax1 = fmaxf(rmax1, fmaxf(sacc[n][2], sacc[n][3]));
        }
#pragma unroll
        for (int w = 1; w < 4; w <<= 1) {
            rmax0 = fmaxf(rmax0, __shfl_xor_sync(0xffffffffu, rmax0, w));
            rmax1 = fmaxf(rmax1, __shfl_xor_sync(0xffffffffu, rmax1, w));
        }
        const float mn0 = fmaxf(m0, rmax0), mn1 = fmaxf(m1, rmax1);
        const float cor0 = __expf(m0 - mn0), cor1 = __expf(m1 - mn1);
        m0 = mn0;
        m1 = mn1;
        float rs0 = 0.f, rs1 = 0.f;
#pragma unroll
        for (int n = 0; n < 16; ++n) {
            sacc[n][0] = __expf(sacc[n][0] - mn0);
            sacc[n][1] = __expf(sacc[n][1] - mn0);
            sacc[n][2] = __expf(sacc[n][2] - mn1);
            sacc[n][3] = __expf(sacc[n][3] - mn1);
            rs0 += sacc[n][0] + sacc[n][1];
            rs1 += sacc[n][2] + sacc[n][3];
        }
#pragma unroll
        for (int w = 1; w < 4; w <<= 1) {
            rs0 += __shfl_xor_sync(0xffffffffu, rs0, w);
            rs1 += __shfl_xor_sync(0xffffffffu, rs1, w);
        }
        l0 = l0 * cor0 + rs0;
        l1 = l1 * cor1 + rs1;
#pragma unroll
        for (int n = 0; n < 8; ++n) {
            oacc[n][0] *= cor0;
            oacc[n][1] *= cor0;
            oacc[n][2] *= cor1;
            oacc[n][3] *= cor1;
        }

        // ---- O += P @ V  (m16 x n64, kv128, 3 split terms) ----
#pragma unroll
        for (int j = 0; j < 8; ++j) {
            uint32_t ah[4], al[4];
            split2(sacc[2 * j][0], sacc[2 * j][1], ah[0], al[0]);
            split2(sacc[2 * j][2], sacc[2 * j][3], ah[1], al[1]);
            split2(sacc[2 * j + 1][0], sacc[2 * j + 1][1], ah[2], al[2]);
            split2(sacc[2 * j + 1][2], sacc[2 * j + 1][3], ah[3], al[3]);
#pragma unroll
            for (int nv = 0; nv < 8; ++nv) {
                const uint32_t voff = (uint32_t)(((j * 16 + l16) * QS + nv * 8) * 2);
                uint32_t bvh[2], bvl[2];
                ldsm_x2t(bvh, sVh + voff);
                ldsm_x2t(bvl, sVl + voff);
                mma_bf16(oacc[nv], ah, bvh);
                mma_bf16(oacc[nv], ah, bvl);
                mma_bf16(oacc[nv], al, bvh);
            }
        }
    }

    // ---- normalize + store [b,h,s,v] ----
    const float inv0 = 1.f / l0, inv1 = 1.f / l1;
    float* orow0 = g_o + (bh + (size_t)(qg0 + r0)) * Kn;
    float* orow1 = orow0 + 8 * Kn;
#pragma unroll
    for (int nv = 0; nv < 8; ++nv) {
        *(float2*)(orow0 + nv * 8 + c2) = make_float2(oacc[nv][0] * inv0, oacc[nv][1] * inv0);
        *(float2*)(orow1 + nv * 8 + c2) = make_float2(oacc[nv][2] * inv1, oacc[nv][3] * inv1);
    }
}

// ---------------------------------------------------------------------------
// 8x8 FFMA micro-kernel helper (projections)
// ---------------------------------------------------------------------------
__device__ __forceinline__ void fma88(float (&acc)[8][8],
                                      const float4 a0, const float4 a1,
                                      const float4 b0, const float4 b1) {
    float a[8] = {a0.x, a0.y, a0.z, a0.w, a1.x, a1.y, a1.z, a1.w};
    float b[8] = {b0.x, b0.y, b0.z, b0.w, b1.x, b1.y, b1.z, b1.w};
#pragma unroll
    for (int i = 0; i < 8; ++i)
#pragma unroll
        for (int j = 0; j < 8; ++j)
            acc[i][j] = fmaf(a[i], b[j], acc[i][j]);
}

// ---------------------------------------------------------------------------
// QKV projection: out[b,h,s,k] = sum_d X[b,s,d] * W[h,d,k], bf16 hi/lo output.
// ---------------------------------------------------------------------------
__global__ __launch_bounds__(256) void proj_kernel(const float* __restrict__ X,
                                                   const float* __restrict__ W,
                                                   __nv_bfloat16* __restrict__ oh,
                                                   __nv_bfloat16* __restrict__ ol) {
    __shared__ float XsT[16][132];
    __shared__ float Bs[16][132];

    const int tid = threadIdx.x;
    const int qr0 = (tid >> 4) * 8;
    const int kc0 = (tid & 15) * 8;
    const int row0 = blockIdx.x * 128;
    const int c0 = blockIdx.y * 128;

    float acc[8][8] = {};

    for (int kk = 0; kk < Dn; kk += 16) {
#pragma unroll
        for (int rep = 0; rep < 2; ++rep) {
            int idx = tid + rep * 256;
            int r = idx >> 2, c = (idx & 3) * 4;
            float4 xv = *(const float4*)(X + (size_t)(row0 + r) * Dn + kk + c);
            XsT[c + 0][r] = xv.x;
            XsT[c + 1][r] = xv.y;
            XsT[c + 2][r] = xv.z;
            XsT[c + 3][r] = xv.w;
        }
#pragma unroll
        for (int rep = 0; rep < 2; ++rep) {
            int idx = tid + rep * 256;
            int kr = idx >> 5, cc = (idx & 31) * 4;
            int col = c0 + cc;
            int h = col >> 6, kidx = col & 63;
            *(float4*)&Bs[kr][cc] =
                *(const float4*)(W + ((size_t)(h * Dn + kk + kr) * Kn) + kidx);
        }
        __syncthreads();
#pragma unroll
        for (int k = 0; k < 16; ++k) {
            float4 a0 = *(const float4*)&XsT[k][qr0];
            float4 a1 = *(const float4*)&XsT[k][qr0 + 4];
            float4 b0 = *(const float4*)&Bs[k][kc0];
            float4 b1 = *(const float4*)&Bs[k][kc0 + 4];
            fma88(acc, a0, a1, b0, b1);
        }
        __syncthreads();
    }

    const int colg = c0 + kc0;
    const int h = colg >> 6, k0 = colg & 63;
#pragma unroll
    for (int i = 0; i < 8; ++i) {
        int row = row0 + qr0 + i;
        int b = row >> 11, s = row & 2047;
        size_t off = (((size_t)(b * Hn + h) * Sn + s) * Kn) + k0;
#pragma unroll
        for (int j = 0; j < 4; ++j) {
            float v0 = acc[i][2 * j], v1 = acc[i][2 * j + 1];
            __nv_bfloat16 h0 = __float2bfloat16(v0);
            __nv_bfloat16 h1 = __float2bfloat16(v1);
            __nv_bfloat16 l0 = __float2bfloat16(v0 - __bfloat162float(h0));
            __nv_bfloat16 l1 = __float2bfloat16(v1 - __bfloat162float(h1));
            *(__nv_bfloat162*)(oh + off + 2 * j) = __halves2bfloat162(h0, h1);
            *(__nv_bfloat162*)(ol + off + 2 * j) = __halves2bfloat162(l0, l1);
        }
    }
}

// ---------------------------------------------------------------------------
// Output projection: out[r, d] = sum_f o_flat[r, f] * W_o[f, d]
// ---------------------------------------------------------------------------
__global__ __launch_bounds__(256) void outproj_kernel(const float* __restrict__ X,
                                                      const float* __restrict__ Wo,
                                                      float* __restrict__ out) {
    __shared__ float XsT[16][132];
    __shared__ float Bs[16][132];

    const int tid = threadIdx.x;
    const int qr0 = (tid >> 4) * 8;
    const int kc0 = (tid & 15) * 8;
    const int row0 = blockIdx.x * 128;
    const int c0 = blockIdx.y * 128;

    float acc[8][8] = {};

    for (int kk = 0; kk < Dn; kk += 16) {
#pragma unroll
        for (int rep = 0; rep < 2; ++rep) {
            int idx = tid + rep * 256;
            int r = idx >> 2, c = (idx & 3) * 4;
            float4 xv = *(const float4*)(X + (size_t)(row0 + r) * Dn + kk + c);
            XsT[c + 0][r] = xv.x;
            XsT[c + 1][r] = xv.y;
            XsT[c + 2][r] = xv.z;
            XsT[c + 3][r] = xv.w;
        }
#pragma unroll
        for (int rep = 0; rep < 2; ++rep) {
            int idx = tid + rep * 256;
            int kr = idx >> 5, cc = (idx & 31) * 4;
            *(float4*)&Bs[kr][cc] =
                *(const float4*)(Wo + (size_t)(kk + kr) * Dn + c0 + cc);
        }
        __syncthreads();
#pragma unroll
        for (int k = 0; k < 16; ++k) {
            float4 a0 = *(const float4*)&XsT[k][qr0];
            float4 a1 = *(const float4*)&XsT[k][qr0 + 4];
            float4 b0 = *(const float4*)&Bs[k][kc0];
            float4 b1 = *(const float4*)&Bs[k][kc0 + 4];
            fma88(acc, a0, a1, b0, b1);
        }
        __syncthreads();
    }

#pragma unroll
    for (int i = 0; i < 8; ++i) {
        float* op = out + (size_t)(row0 + qr0 + i) * Dn + c0 + kc0;
        *(float4*)op = make_float4(acc[i][0], acc[i][1], acc[i][2], acc[i][3]);
        *(float4*)(op + 4) = make_float4(acc[i][4], acc[i][5], acc[i][6], acc[i][7]);
    }
}

// ---------------------------------------------------------------------------
extern "C" void kernel_launch(void* const* d_in, const int* in_sizes, int n_in,
                              void* d_out, int out_size) {
    const float* queries = (const float*)d_in[0];
    const float* keys    = (const float*)d_in[1];
    const float* values  = (const float*)d_in[2];
    const float* mask    = (const float*)d_in[3];
    const float* W_q     = (const float*)d_in[4];
    const float* W_k     = (const float*)d_in[5];
    const float* W_v     = (const float*)d_in[6];
    const float* W_o     = (const float*)d_in[7];
    float* out = (float*)d_out;

    __nv_bfloat16 *qh, *ql, *kh, *kl, *vh, *vl;
    float* go;
    cudaGetSymbolAddress((void**)&qh, g_qh);
    cudaGetSymbolAddress((void**)&ql, g_ql);
    cudaGetSymbolAddress((void**)&kh, g_kh);
    cudaGetSymbolAddress((void**)&kl, g_kl);
    cudaGetSymbolAddress((void**)&vh, g_vh);
    cudaGetSymbolAddress((void**)&vl, g_vl);
    cudaGetSymbolAddress((void**)&go, g_o);

    cudaFuncSetAttribute(attn_kernel, cudaFuncAttributeMaxDynamicSharedMemorySize, ATTN_SMEM);

    dim3 gproj(Bn * Sn / 128, Dn / 128);  // (64, 6)
    proj_kernel<<<gproj, 256>>>(queries, W_q, qh, ql);
    proj_kernel<<<gproj, 256>>>(keys,    W_k, kh, kl);
    proj_kernel<<<gproj, 256>>>(values,  W_v, vh, vl);

    dim3 gattn(Sn / 128, Hn, Bn);  // (16, 12, 4)
    attn_kernel<<<gattn, 256, ATTN_SMEM>>>(mask);

    dim3 gout(Bn * Sn / 128, Dn / 128);  // (64, 6)
    outproj_kernel<<<gout, 256>>>(go, W_o, out);
}

// round 6
// speedup vs baseline: 2.2852x; 1.4143x over previous
#include <cuda_runtime.h>
#include <cuda_bf16.h>
#include <cstdint>

#define Bn 4
#define Sn 2048
#define Dn 768
#define Hn 12
#define Kn 64
#define NELEM (Bn * Hn * Sn * Kn)

// Scratch device globals (no cudaMalloc allowed).
__device__ __nv_bfloat16 g_qh[NELEM], g_ql[NELEM];
__device__ __nv_bfloat16 g_kh[NELEM], g_kl[NELEM];
__device__ __nv_bfloat16 g_vh[NELEM], g_vl[NELEM];
__device__ __nv_bfloat16 g_oh[NELEM], g_ol[NELEM];

// ---------------------------------------------------------------------------
// helpers
// ---------------------------------------------------------------------------
__device__ __forceinline__ uint32_t smem_u32(const void* p) {
    uint32_t a;
    asm("{ .reg .u64 t; cvta.to.shared.u64 t, %1; cvt.u32.u64 %0, t; }" : "=r"(a) : "l"(p));
    return a;
}
__device__ __forceinline__ void ldsm_x4(uint32_t (&r)[4], uint32_t addr) {
    asm volatile("ldmatrix.sync.aligned.m8n8.x4.shared.b16 {%0,%1,%2,%3}, [%4];"
                 : "=r"(r[0]), "=r"(r[1]), "=r"(r[2]), "=r"(r[3]) : "r"(addr));
}
__device__ __forceinline__ void ldsm_x4t(uint32_t (&r)[4], uint32_t addr) {
    asm volatile("ldmatrix.sync.aligned.m8n8.x4.trans.shared.b16 {%0,%1,%2,%3}, [%4];"
                 : "=r"(r[0]), "=r"(r[1]), "=r"(r[2]), "=r"(r[3]) : "r"(addr));
}
__device__ __forceinline__ void ldsm_x2(uint32_t (&r)[2], uint32_t addr) {
    asm volatile("ldmatrix.sync.aligned.m8n8.x2.shared.b16 {%0,%1}, [%2];"
                 : "=r"(r[0]), "=r"(r[1]) : "r"(addr));
}
__device__ __forceinline__ void ldsm_x2t(uint32_t (&r)[2], uint32_t addr) {
    asm volatile("ldmatrix.sync.aligned.m8n8.x2.trans.shared.b16 {%0,%1}, [%2];"
                 : "=r"(r[0]), "=r"(r[1]) : "r"(addr));
}
__device__ __forceinline__ void mma_bf16(float (&d)[4], const uint32_t (&a)[4],
                                         const uint32_t (&b)[2]) {
    asm volatile(
        "mma.sync.aligned.m16n8k16.row.col.f32.bf16.bf16.f32 "
        "{%0,%1,%2,%3}, {%4,%5,%6,%7}, {%8,%9}, {%0,%1,%2,%3};"
        : "+f"(d[0]), "+f"(d[1]), "+f"(d[2]), "+f"(d[3])
        : "r"(a[0]), "r"(a[1]), "r"(a[2]), "r"(a[3]), "r"(b[0]), "r"(b[1]));
}
__device__ __forceinline__ void split2(float x, float y, uint32_t& h, uint32_t& l) {
    __nv_bfloat16 hx = __float2bfloat16(x), hy = __float2bfloat16(y);
    __nv_bfloat16 lx = __float2bfloat16(x - __bfloat162float(hx));
    __nv_bfloat16 ly = __float2bfloat16(y - __bfloat162float(hy));
    __nv_bfloat162 hh = __halves2bfloat162(hx, hy);
    __nv_bfloat162 ll = __halves2bfloat162(lx, ly);
    h = *(uint32_t*)&hh;
    l = *(uint32_t*)&ll;
}

// ===========================================================================
// mma.sync GEMM core: C[128 x 128] tile, BK=32, 8 warps (m32 x n64 each).
// A smem: row-major [128][AS]; B smem: k-major [32][BSS] (ldsm trans).
// ===========================================================================
#define AS 40
#define BSS 136

struct MmaCtx {
    int wm, wn, l16, grp, lane;
};

__device__ __forceinline__ void mma_kblock(float (&acc)[2][8][4],
                                           uint32_t sAh, uint32_t sAl,
                                           uint32_t sBh, uint32_t sBl,
                                           const MmaCtx& c) {
#pragma unroll
    for (int ks = 0; ks < 32; ks += 16) {
        uint32_t ah[2][4], al[2][4];
#pragma unroll
        for (int mi = 0; mi < 2; ++mi) {
            const uint32_t aoff =
                (uint32_t)(((c.wm + mi * 16 + c.l16) * AS + ks + (c.lane >> 4) * 8) * 2);
            ldsm_x4(ah[mi], sAh + aoff);
            ldsm_x4(al[mi], sAl + aoff);
        }
        uint32_t bh[8][2], bl[8][2];
#pragma unroll
        for (int nb = 0; nb < 4; ++nb) {
            const uint32_t boff =
                (uint32_t)(((ks + (c.grp & 1) * 8 + (c.lane & 7)) * BSS +
                            c.wn + nb * 16 + (c.grp >> 1) * 8) * 2);
            uint32_t rh[4], rl[4];
            ldsm_x4t(rh, sBh + boff);
            ldsm_x4t(rl, sBl + boff);
            bh[2 * nb][0] = rh[0]; bh[2 * nb][1] = rh[1];
            bh[2 * nb + 1][0] = rh[2]; bh[2 * nb + 1][1] = rh[3];
            bl[2 * nb][0] = rl[0]; bl[2 * nb][1] = rl[1];
            bl[2 * nb + 1][0] = rl[2]; bl[2 * nb + 1][1] = rl[3];
        }
#pragma unroll
        for (int mi = 0; mi < 2; ++mi)
#pragma unroll
            for (int nj = 0; nj < 8; ++nj) {
                mma_bf16(acc[mi][nj], ah[mi], bh[nj]);
                mma_bf16(acc[mi][nj], ah[mi], bl[nj]);
                mma_bf16(acc[mi][nj], al[mi], bh[nj]);
            }
    }
}

// ---------------------------------------------------------------------------
// QKV projection (tensor cores): out[b,h,s,k] = sum_d X[b,s,d]*W[h,d,k],
// hi/lo bf16 output. Grid (64, 6), 256 threads.
// ---------------------------------------------------------------------------
__global__ __launch_bounds__(256) void proj_mma(const float* __restrict__ X,
                                                const float* __restrict__ W,
                                                __nv_bfloat16* __restrict__ oh,
                                                __nv_bfloat16* __restrict__ ol) {
    __shared__ __nv_bfloat16 Ah[128 * AS], Al[128 * AS];
    __shared__ __nv_bfloat16 Bh[32 * BSS], Bl[32 * BSS];
    const uint32_t sAh = smem_u32(Ah), sAl = smem_u32(Al);
    const uint32_t sBh = smem_u32(Bh), sBl = smem_u32(Bl);

    const int tid = threadIdx.x;
    const int wid = tid >> 5, lane = tid & 31;
    MmaCtx c{(wid >> 1) * 32, (wid & 1) * 64, lane & 15, lane >> 3, lane};
    const int r0 = lane >> 2, c2 = (lane & 3) * 2;
    const int row0 = blockIdx.x * 128, c0 = blockIdx.y * 128;

    float acc[2][8][4] = {};

    for (int kk = 0; kk < Dn; kk += 32) {
        __syncthreads();
        // A: 128 x 32 fp32, split -> Ah/Al
#pragma unroll
        for (int rep = 0; rep < 4; ++rep) {
            int idx = tid + rep * 256;
            int r = idx >> 3, kc = (idx & 7) * 4;
            float4 xv = *(const float4*)(X + (size_t)(row0 + r) * Dn + kk + kc);
            uint32_t h0, l0, h1, l1;
            split2(xv.x, xv.y, h0, l0);
            split2(xv.z, xv.w, h1, l1);
            *(uint2*)&Ah[r * AS + kc] = make_uint2(h0, h1);
            *(uint2*)&Al[r * AS + kc] = make_uint2(l0, l1);
        }
        // B: 32 x 128 fp32 (k-major, col -> (h, kidx)), split -> Bh/Bl
#pragma unroll
        for (int rep = 0; rep < 8; ++rep) {
            int idx = tid + rep * 256;
            int k = idx >> 6, col = (idx & 63) * 2;
            int colg = c0 + col;
            int h = colg >> 6, kidx = colg & 63;
            float2 wv = *(const float2*)(W + (size_t)(h * Dn + kk + k) * Kn + kidx);
            uint32_t bh, bl;
            split2(wv.x, wv.y, bh, bl);
            *(uint32_t*)&Bh[k * BSS + col] = bh;
            *(uint32_t*)&Bl[k * BSS + col] = bl;
        }
        __syncthreads();
        mma_kblock(acc, sAh, sAl, sBh, sBl, c);
    }

    // epilogue: split + scatter to [b,h,s,k]
#pragma unroll
    for (int mi = 0; mi < 2; ++mi)
#pragma unroll
        for (int rr = 0; rr < 2; ++rr) {
            int row = row0 + c.wm + mi * 16 + r0 + rr * 8;
            int b = row >> 11, s = row & 2047;
#pragma unroll
            for (int nj = 0; nj < 8; ++nj) {
                int colg = c0 + c.wn + nj * 8 + c2;
                int h = colg >> 6, k0 = colg & 63;
                size_t off = (((size_t)(b * Hn + h) * Sn + s) * Kn) + k0;
                uint32_t hv, lv;
                split2(acc[mi][nj][2 * rr], acc[mi][nj][2 * rr + 1], hv, lv);
                *(uint32_t*)(oh + off) = hv;
                *(uint32_t*)(ol + off) = lv;
            }
        }
}

// ---------------------------------------------------------------------------
// Output projection (tensor cores): out[r,d] = sum_f o[r,f]*Wo[f,d].
// A comes pre-split (g_oh/g_ol read raw as [8192][768]).
// ---------------------------------------------------------------------------
__global__ __launch_bounds__(256) void outproj_mma(const __nv_bfloat16* __restrict__ Xh,
                                                   const __nv_bfloat16* __restrict__ Xl,
                                                   const float* __restrict__ Wo,
                                                   float* __restrict__ out) {
    __shared__ __nv_bfloat16 Ah[128 * AS], Al[128 * AS];
    __shared__ __nv_bfloat16 Bh[32 * BSS], Bl[32 * BSS];
    const uint32_t sAh = smem_u32(Ah), sAl = smem_u32(Al);
    const uint32_t sBh = smem_u32(Bh), sBl = smem_u32(Bl);

    const int tid = threadIdx.x;
    const int wid = tid >> 5, lane = tid & 31;
    MmaCtx c{(wid >> 1) * 32, (wid & 1) * 64, lane & 15, lane >> 3, lane};
    const int r0 = lane >> 2, c2 = (lane & 3) * 2;
    const int row0 = blockIdx.x * 128, c0 = blockIdx.y * 128;

    float acc[2][8][4] = {};

    for (int kk = 0; kk < Dn; kk += 32) {
        __syncthreads();
        // A: 128 x 32 bf16 (already split)
#pragma unroll
        for (int rep = 0; rep < 2; ++rep) {
            int idx = tid + rep * 256;
            int r = idx >> 2, kc = (idx & 3) * 8;
            *(uint4*)&Ah[r * AS + kc] = *(const uint4*)(Xh + (size_t)(row0 + r) * Dn + kk + kc);
            *(uint4*)&Al[r * AS + kc] = *(const uint4*)(Xl + (size_t)(row0 + r) * Dn + kk + kc);
        }
        // B: 32 x 128 fp32 k-major
#pragma unroll
        for (int rep = 0; rep < 8; ++rep) {
            int idx = tid + rep * 256;
            int k = idx >> 6, col = (idx & 63) * 2;
            float2 wv = *(const float2*)(Wo + (size_t)(kk + k) * Dn + c0 + col);
            uint32_t bh, bl;
            split2(wv.x, wv.y, bh, bl);
            *(uint32_t*)&Bh[k * BSS + col] = bh;
            *(uint32_t*)&Bl[k * BSS + col] = bl;
        }
        __syncthreads();
        mma_kblock(acc, sAh, sAl, sBh, sBl, c);
    }

#pragma unroll
    for (int mi = 0; mi < 2; ++mi)
#pragma unroll
        for (int rr = 0; rr < 2; ++rr) {
            int row = row0 + c.wm + mi * 16 + r0 + rr * 8;
#pragma unroll
            for (int nj = 0; nj < 8; ++nj) {
                int colg = c0 + c.wn + nj * 8 + c2;
                *(float2*)(out + (size_t)row * Dn + colg) =
                    make_float2(acc[mi][nj][2 * rr], acc[mi][nj][2 * rr + 1]);
            }
        }
}

// ===========================================================================
// mma.sync flash attention per (b, h, q-tile of 128); k-tiles of 128.
// 256 threads = 8 warps, warp w owns q rows [16w, 16w+16).
// ===========================================================================
#define QS 72
#define TILE_E (128 * QS)
#define ATTN_SMEM (6 * TILE_E * 2)

__global__ __launch_bounds__(256, 1) void attn_kernel(const float* __restrict__ mask) {
    extern __shared__ __nv_bfloat16 smbf[];
    __nv_bfloat16* Qh = smbf;
    __nv_bfloat16* Ql = Qh + TILE_E;
    __nv_bfloat16* Kh = Ql + TILE_E;
    __nv_bfloat16* Kl = Kh + TILE_E;
    __nv_bfloat16* Vh = Kl + TILE_E;
    __nv_bfloat16* Vl = Vh + TILE_E;

    const uint32_t sQh = smem_u32(Qh), sQl = smem_u32(Ql);
    const uint32_t sKh = smem_u32(Kh), sKl = smem_u32(Kl);
    const uint32_t sVh = smem_u32(Vh), sVl = smem_u32(Vl);

    const int tid = threadIdx.x;
    const int wid = tid >> 5, lane = tid & 31;
    const int l16 = lane & 15;
    const int r0 = lane >> 2;
    const int c2 = (lane & 3) * 2;
    const int qt = blockIdx.x, hd = blockIdx.y, b = blockIdx.z;
    const size_t bh = (size_t)(b * Hn + hd) * Sn;
    const int qr0 = wid * 16;
    const int qg0 = qt * 128 + qr0;

    {
        const __nv_bfloat16* qh = g_qh + (bh + (size_t)qt * 128) * Kn;
        const __nv_bfloat16* ql = g_ql + (bh + (size_t)qt * 128) * Kn;
#pragma unroll
        for (int rep = 0; rep < 4; ++rep) {
            int idx = tid + rep * 256;
            int r = idx >> 3, c8 = (idx & 7) * 8;
            *(uint4*)(Qh + r * QS + c8) = *(const uint4*)(qh + r * 64 + c8);
            *(uint4*)(Ql + r * QS + c8) = *(const uint4*)(ql + r * 64 + c8);
        }
    }

    float oacc[8][4];
#pragma unroll
    for (int n = 0; n < 8; ++n)
#pragma unroll
        for (int j = 0; j < 4; ++j) oacc[n][j] = 0.f;
    float m0 = -1e30f, m1 = -1e30f, l0 = 0.f, l1 = 0.f;

    const float* mp0 = mask + (size_t)(qg0 + r0) * Sn;
    const float* mp1 = mp0 + 8 * Sn;
    const float scale = 0.125f;

    for (int kt = 0; kt < Sn / 128; ++kt) {
        __syncthreads();
        {
            const __nv_bfloat16* kh = g_kh + (bh + (size_t)kt * 128) * Kn;
            const __nv_bfloat16* kl = g_kl + (bh + (size_t)kt * 128) * Kn;
            const __nv_bfloat16* vh = g_vh + (bh + (size_t)kt * 128) * Kn;
            const __nv_bfloat16* vl = g_vl + (bh + (size_t)kt * 128) * Kn;
#pragma unroll
            for (int rep = 0; rep < 4; ++rep) {
                int idx = tid + rep * 256;
                int r = idx >> 3, c8 = (idx & 7) * 8;
                *(uint4*)(Kh + r * QS + c8) = *(const uint4*)(kh + r * 64 + c8);
                *(uint4*)(Kl + r * QS + c8) = *(const uint4*)(kl + r * 64 + c8);
                *(uint4*)(Vh + r * QS + c8) = *(const uint4*)(vh + r * 64 + c8);
                *(uint4*)(Vl + r * QS + c8) = *(const uint4*)(vl + r * 64 + c8);
            }
        }
        __syncthreads();

        // S = Q @ K^T
        float sacc[16][4];
#pragma unroll
        for (int n = 0; n < 16; ++n)
#pragma unroll
            for (int j = 0; j < 4; ++j) sacc[n][j] = 0.f;

#pragma unroll
        for (int ks = 0; ks < 4; ++ks) {
            uint32_t aqh[4], aql[4];
            const uint32_t aoff =
                (uint32_t)(((qr0 + l16) * QS + ks * 16 + (lane >> 4) * 8) * 2);
            ldsm_x4(aqh, sQh + aoff);
            ldsm_x4(aql, sQl + aoff);
#pragma unroll
            for (int n = 0; n < 16; ++n) {
                const uint32_t boff =
                    (uint32_t)(((n * 8 + (l16 & 7)) * QS + ks * 16 + (l16 >> 3) * 8) * 2);
                uint32_t bkh[2], bkl[2];
                ldsm_x2(bkh, sKh + boff);
                ldsm_x2(bkl, sKl + boff);
                mma_bf16(sacc[n], aqh, bkh);
                mma_bf16(sacc[n], aqh, bkl);
                mma_bf16(sacc[n], aql, bkh);
            }
        }

        // scale + mask bias + online softmax
        float rmax0 = -1e30f, rmax1 = -1e30f;
#pragma unroll
        for (int n = 0; n < 16; ++n) {
            const int col = kt * 128 + n * 8 + c2;
            float2 mv0 = __ldg((const float2*)(mp0 + col));
            float2 mv1 = __ldg((const float2*)(mp1 + col));
            sacc[n][0] = fmaf(sacc[n][0], scale, (1.f - mv0.x) * -1e9f);
            sacc[n][1] = fmaf(sacc[n][1], scale, (1.f - mv0.y) * -1e9f);
            sacc[n][2] = fmaf(sacc[n][2], scale, (1.f - mv1.x) * -1e9f);
            sacc[n][3] = fmaf(sacc[n][3], scale, (1.f - mv1.y) * -1e9f);
            rmax0 = fmaxf(rmax0, fmaxf(sacc[n][0], sacc[n][1]));
            rmax1 = fmaxf(rmax1, fmaxf(sacc[n][2], sacc[n][3]));
        }
#pragma unroll
        for (int w = 1; w < 4; w <<= 1) {
            rmax0 = fmaxf(rmax0, __shfl_xor_sync(0xffffffffu, rmax0, w));
            rmax1 = fmaxf(rmax1, __shfl_xor_sync(0xffffffffu, rmax1, w));
        }
        const float mn0 = fmaxf(m0, rmax0), mn1 = fmaxf(m1, rmax1);
        const float cor0 = __expf(m0 - mn0), cor1 = __expf(m1 - mn1);
        m0 = mn0;
        m1 = mn1;
        float rs0 = 0.f, rs1 = 0.f;
#pragma unroll
        for (int n = 0; n < 16; ++n) {
            sacc[n][0] = __expf(sacc[n][0] - mn0);
            sacc[n][1] = __expf(sacc[n][1] - mn0);
            sacc[n][2] = __expf(sacc[n][2] - mn1);
            sacc[n][3] = __expf(sacc[n][3] - mn1);
            rs0 += sacc[n][0] + sacc[n][1];
            rs1 += sacc[n][2] + sacc[n][3];
        }
#pragma unroll
        for (int w = 1; w < 4; w <<= 1) {
            rs0 += __shfl_xor_sync(0xffffffffu, rs0, w);
            rs1 += __shfl_xor_sync(0xffffffffu, rs1, w);
        }
        l0 = l0 * cor0 + rs0;
        l1 = l1 * cor1 + rs1;
#pragma unroll
        for (int n = 0; n < 8; ++n) {
            oacc[n][0] *= cor0;
            oacc[n][1] *= cor0;
            oacc[n][2] *= cor1;
            oacc[n][3] *= cor1;
        }

        // O += P @ V
#pragma unroll
        for (int j = 0; j < 8; ++j) {
            uint32_t ah[4], al[4];
            split2(sacc[2 * j][0], sacc[2 * j][1], ah[0], al[0]);
            split2(sacc[2 * j][2], sacc[2 * j][3], ah[1], al[1]);
            split2(sacc[2 * j + 1][0], sacc[2 * j + 1][1], ah[2], al[2]);
            split2(sacc[2 * j + 1][2], sacc[2 * j + 1][3], ah[3], al[3]);
#pragma unroll
            for (int nv = 0; nv < 8; ++nv) {
                const uint32_t voff = (uint32_t)(((j * 16 + l16) * QS + nv * 8) * 2);
                uint32_t bvh[2], bvl[2];
                ldsm_x2t(bvh, sVh + voff);
                ldsm_x2t(bvl, sVl + voff);
                mma_bf16(oacc[nv], ah, bvh);
                mma_bf16(oacc[nv], ah, bvl);
                mma_bf16(oacc[nv], al, bvh);
            }
        }
    }

    // normalize + split + store hi/lo bf16 [b,h,s,v]
    const float inv0 = 1.f / l0, inv1 = 1.f / l1;
    const size_t off0 = (bh + (size_t)(qg0 + r0)) * Kn;
    const size_t off1 = off0 + 8 * Kn;
#pragma unroll
    for (int nv = 0; nv < 8; ++nv) {
        uint32_t h0, l0v, h1, l1v;
        split2(oacc[nv][0] * inv0, oacc[nv][1] * inv0, h0, l0v);
        split2(oacc[nv][2] * inv1, oacc[nv][3] * inv1, h1, l1v);
        *(uint32_t*)(g_oh + off0 + nv * 8 + c2) = h0;
        *(uint32_t*)(g_ol + off0 + nv * 8 + c2) = l0v;
        *(uint32_t*)(g_oh + off1 + nv * 8 + c2) = h1;
        *(uint32_t*)(g_ol + off1 + nv * 8 + c2) = l1v;
    }
}

// ---------------------------------------------------------------------------
extern "C" void kernel_launch(void* const* d_in, const int* in_sizes, int n_in,
                              void* d_out, int out_size) {
    const float* queries = (const float*)d_in[0];
    const float* keys    = (const float*)d_in[1];
    const float* values  = (const float*)d_in[2];
    const float* mask    = (const float*)d_in[3];
    const float* W_q     = (const float*)d_in[4];
    const float* W_k     = (const float*)d_in[5];
    const float* W_v     = (const float*)d_in[6];
    const float* W_o     = (const float*)d_in[7];
    float* out = (float*)d_out;

    __nv_bfloat16 *qh, *ql, *kh, *kl, *vh, *vl, *oh, *ol;
    cudaGetSymbolAddress((void**)&qh, g_qh);
    cudaGetSymbolAddress((void**)&ql, g_ql);
    cudaGetSymbolAddress((void**)&kh, g_kh);
    cudaGetSymbolAddress((void**)&kl, g_kl);
    cudaGetSymbolAddress((void**)&vh, g_vh);
    cudaGetSymbolAddress((void**)&vl, g_vl);
    cudaGetSymbolAddress((void**)&oh, g_oh);
    cudaGetSymbolAddress((void**)&ol, g_ol);

    cudaFuncSetAttribute(attn_kernel, cudaFuncAttributeMaxDynamicSharedMemorySize, ATTN_SMEM);

    dim3 gproj(Bn * Sn / 128, Dn / 128);  // (64, 6)
    proj_mma<<<gproj, 256>>>(queries, W_q, qh, ql);
    proj_mma<<<gproj, 256>>>(keys,    W_k, kh, kl);
    proj_mma<<<gproj, 256>>>(values,  W_v, vh, vl);

    dim3 gattn(Sn / 128, Hn, Bn);  // (16, 12, 4)
    attn_kernel<<<gattn, 256, ATTN_SMEM>>>(mask);

    dim3 gout(Bn * Sn / 128, Dn / 128);  // (64, 6)
    outproj_mma<<<gout, 256>>>(oh, ol, W_o, out);
}